// round 7
// baseline (speedup 1.0000x reference)
#include <cuda_runtime.h>
#include <math.h>
#include <stdint.h>

constexpr int B_    = 512;
constexpr int LEN_  = 1000;
constexpr int D_    = 16;
constexpr int HID_  = 256;
constexpr int WIN_  = 64;
constexpr int PAIRS_  = 120;
constexpr int LOGSIG_ = 136;
constexpr int K1_   = HID_ + LOGSIG_;   // 392
constexpr int K1P_  = 416;              // 13*32
constexpr int BT_   = 16;               // batch rows per CTA
constexpr int NCH_  = 32;               // cumsum time chunks
constexpr int WROW_ = 36;               // padded W row (floats)
constexpr int WT_   = 256 * WROW_;      // one W tile buffer (floats)

__device__ float g_X[(size_t)B_ * LEN_ * D_];
__device__ float g_ls[(size_t)WIN_ * B_ * LOGSIG_];
__device__ float g_last[2][(size_t)B_ * HID_];
__device__ float g_part[(size_t)B_ * NCH_ * D_];
__device__ float g_dts[LEN_ - 1];
__device__ int   g_tidx[WIN_ - 1];
__device__ int   g_sidx[WIN_ - 1];
__device__ int   g_iu[PAIRS_];
__device__ int   g_ju[PAIRS_];

__host__ __device__ __forceinline__ double tb_d(int i) {
    return (i == LEN_ - 1) ? 1.0 : (double)i * (1.0 / 999.0);
}
__host__ __device__ __forceinline__ double tt_d(int k) {
    return (k == WIN_ - 1) ? 1.0 : (double)k * (1.0 / 63.0);
}

__global__ void sched_kernel() {
    int tid = threadIdx.x;
    for (int i = tid; i < LEN_ - 1; i += blockDim.x)
        g_dts[i] = sqrtf((float)(tb_d(i + 1) - tb_d(i)));
    if (tid < WIN_ - 1) {
        double t = tt_d(tid + 1);
        int ti = 0;
        for (int i = 0; i < LEN_; i++) if (tb_d(i) <= t) ti = i;
        g_tidx[tid] = ti;
        int uj = 0;
        for (int j = 0; j < LEN_ / 50; j++) if (tb_d(50 * j) <= t) uj = j;
        g_sidx[tid] = 50 * uj;
    }
    if (tid >= 64 && tid < 64 + PAIRS_) {
        int p = tid - 64;
        int i = 0, accp = 0;
        while (accp + (D_ - 1 - i) <= p) { accp += D_ - 1 - i; i++; }
        g_iu[p] = i;
        g_ju[p] = i + 1 + (p - accp);
    }
}

__global__ void zero_last_kernel() {
    int g = blockIdx.x * blockDim.x + threadIdx.x;
    if (g < B_ * HID_) g_last[0][g] = 0.f;
}

// chunk c covers t in ((c*999)/32, ((c+1)*999)/32]
__device__ __forceinline__ void chunk_rng(int c, int& t0, int& t1) {
    t0 = (c * 999) / NCH_ + 1;
    t1 = ((c + 1) * 999) / NCH_;
}

// thread handles a float4 of d; B*NCH*4 threads
__global__ void cumsum_part_kernel(const float* __restrict__ z) {
    int g = blockIdx.x * blockDim.x + threadIdx.x;
    int d4 = g & 3, c = (g >> 2) & (NCH_ - 1), b = g >> 7;
    int t0, t1; chunk_rng(c, t0, t1);
    const float4* zp = reinterpret_cast<const float4*>(z + (size_t)b * LEN_ * D_) + d4;
    float4 s = make_float4(0.f, 0.f, 0.f, 0.f);
    for (int t = t0; t <= t1; t++) {
        float dt = g_dts[t - 1];
        float4 zv = zp[t * 4];
        s.x += zv.x * dt; s.y += zv.y * dt; s.z += zv.z * dt; s.w += zv.w * dt;
    }
    reinterpret_cast<float4*>(g_part + ((size_t)b * NCH_ + c) * D_)[d4] = s;
}

__global__ void cumsum_write_kernel(const float* __restrict__ z) {
    int g = blockIdx.x * blockDim.x + threadIdx.x;
    int d4 = g & 3, c = (g >> 2) & (NCH_ - 1), b = g >> 7;
    float4 acc = make_float4(0.f, 0.f, 0.f, 0.f);
    for (int cc = 0; cc < c; cc++) {
        float4 p = reinterpret_cast<const float4*>(g_part + ((size_t)b * NCH_ + cc) * D_)[d4];
        acc.x += p.x; acc.y += p.y; acc.z += p.z; acc.w += p.w;
    }
    int t0, t1; chunk_rng(c, t0, t1);
    const float4* zp = reinterpret_cast<const float4*>(z + (size_t)b * LEN_ * D_) + d4;
    float4* xp = reinterpret_cast<float4*>(g_X + (size_t)b * LEN_ * D_) + d4;
    if (c == 0) xp[0] = make_float4(0.f, 0.f, 0.f, 0.f);
    for (int t = t0; t <= t1; t++) {
        float dt = g_dts[t - 1];
        float4 zv = zp[t * 4];
        acc.x += zv.x * dt; acc.y += zv.y * dt; acc.z += zv.z * dt; acc.w += zv.w * dt;
        xp[t * 4] = acc;
    }
}

__global__ void logsig_kernel() {
    int kk = blockIdx.x, b = blockIdx.y, tid = threadIdx.x;
    if (kk == 0) {
        if (tid < LOGSIG_) g_ls[(size_t)b * LOGSIG_ + tid] = 0.f;
        return;
    }
    int k = kk - 1, t1 = g_tidx[k], s0 = g_sidx[k];
    int nrow = t1 - s0 + 1;                          // <= 50
    __shared__ float sX[50 * 16];
    const float* xb = g_X + ((size_t)b * LEN_ + s0) * D_;
    for (int e = tid; e < (nrow * D_) >> 2; e += blockDim.x)
        reinterpret_cast<float4*>(sX)[e] = reinterpret_cast<const float4*>(xb)[e];
    __syncthreads();
    float* outp = g_ls + ((size_t)kk * B_ + b) * LOGSIG_;
    if (tid < D_) {
        outp[tid] = sX[(t1 - s0) * D_ + tid];
    } else if (tid < LOGSIG_) {
        int p = tid - D_, iu = g_iu[p], ju = g_ju[p];
        float xi = sX[iu], xj = sX[ju];
        float acc = 0.f;
        for (int s = 1; s < nrow; s++) {
            float yi = sX[s * D_ + iu], yj = sX[s * D_ + ju];
            acc += xi * (yj - xj) - xj * (yi - xi);
            xi = yi; xj = yj;
        }
        outp[tid] = 0.5f * acc;
    }
}

// ---- stage one 256x32 W chunk into pad-36 rows (512 threads) ----
__device__ __forceinline__ void stage_chunk(const float* __restrict__ Wg, int Ktrue,
                                            int k0, float* sWbuf, int tid) {
    #pragma unroll
    for (int u = 0; u < 4; u++) {
        int g = (u << 9) + tid;          // 2048 float4s
        int row = g >> 3;
        int c4  = g & 7;
        int k   = k0 + (c4 << 2);
        uint32_t dst = (uint32_t)__cvta_generic_to_shared(sWbuf + row * WROW_ + (c4 << 2));
        bool valid = (k + 4 <= Ktrue);
        const float* src = valid ? (Wg + (size_t)row * Ktrue + k) : Wg;
        int sz = valid ? 16 : 0;
        asm volatile("cp.async.cg.shared.global [%0], [%1], 16, %2;"
                     :: "r"(dst), "l"(src), "r"(sz));
    }
    asm volatile("cp.async.commit_group;");
}

__device__ __forceinline__ void ffma2(unsigned long long& acc,
                                      unsigned long long a, unsigned long long b) {
    asm("fma.rn.f32x2 %0, %1, %2, %0;" : "+l"(acc) : "l"(a), "l"(b));
}

// GEMM: thread owns output column j (= tid&255) and 8 rows (r0 = (tid>>8)*8).
// W chunk lives in registers (lane-distinct); x read as broadcast LDS.128.
__device__ __forceinline__ void gemm_j(
    const float* __restrict__ Wg, int Ktrue, int nch,
    const float* __restrict__ sin, int sstride,
    float* __restrict__ sW, int tid, int j, int r0, float outv[8])
{
    unsigned long long acc[8];
    #pragma unroll
    for (int r = 0; r < 8; r++) acc[r] = 0ULL;

    stage_chunk(Wg, Ktrue, 0, sW, tid);
    for (int ch = 0; ch < nch; ch++) {
        if (ch + 1 < nch) {
            stage_chunk(Wg, Ktrue, (ch + 1) << 5, sW + ((ch + 1) & 1) * WT_, tid);
            asm volatile("cp.async.wait_group 1;");
        } else {
            asm volatile("cp.async.wait_group 0;");
        }
        __syncthreads();
        const float* cur = sW + (ch & 1) * WT_;
        const int k0 = ch << 5;

        ulonglong2 w2[8];
        #pragma unroll
        for (int q = 0; q < 8; q++)
            w2[q] = *reinterpret_cast<const ulonglong2*>(cur + j * WROW_ + (q << 2));

        #pragma unroll
        for (int r = 0; r < 8; r++) {
            const float* xr = sin + (r0 + r) * sstride + k0;
            #pragma unroll
            for (int q = 0; q < 8; q++) {
                ulonglong2 x2 = *reinterpret_cast<const ulonglong2*>(xr + (q << 2));
                ffma2(acc[r], w2[q].x, x2.x);
                ffma2(acc[r], w2[q].y, x2.y);
            }
        }
        __syncthreads();
    }
    #pragma unroll
    for (int r = 0; r < 8; r++) {
        float lo = __uint_as_float((unsigned)acc[r]);
        float hi = __uint_as_float((unsigned)(acc[r] >> 32));
        outv[r] = lo + hi;
    }
}

// One launch = one constant-last_h segment; CTA = 16 rows, 512 threads, 4-layer MLP.
__global__ void __launch_bounds__(512, 1)
rnn_round_kernel(const float* __restrict__ W1, const float* __restrict__ b1,
                 const float* __restrict__ W2, const float* __restrict__ b2,
                 const float* __restrict__ W3, const float* __restrict__ b3,
                 const float* __restrict__ Wl, float* __restrict__ out,
                 int parity, int step0, int seglen)
{
    extern __shared__ float smem[];
    float* sW = smem;                       // 2 * 256*36
    float* R0 = sW + 2 * WT_;               // 16*416 (input, later relu2)
    float* R1 = R0 + BT_ * K1P_;            // 16*256 (relu1, later h)

    const float* last_in  = g_last[parity];
    float*       last_out = g_last[parity ^ 1];

    const int tid  = threadIdx.x;
    const int j    = tid & 255;
    const int r0   = (tid >> 8) * 8;
    const int base = blockIdx.x * BT_;
    const int step = step0 + (base >> 9);
    const int b0   = base & 511;
    const bool is_last = (step == step0 + seglen - 1);

    // stage concat(last_h, logsig) -> R0 rows of 416 (zero pad 392..415)
    for (int r = 0; r < BT_; r++) {
        int b = b0 + r;
        for (int c = tid; c < K1P_; c += 512) {
            float v = 0.f;
            if (c < HID_)     v = last_in[(size_t)b * HID_ + c];
            else if (c < K1_) v = g_ls[((size_t)step * B_ + b) * LOGSIG_ + (c - HID_)];
            R0[r * K1P_ + c] = v;
        }
    }

    float v[8];

    gemm_j(W1, K1_, K1P_ / 32, R0, K1P_, sW, tid, j, r0, v);
    {
        float bb = b1[j];
        #pragma unroll
        for (int r = 0; r < 8; r++)
            R1[(r0 + r) * HID_ + j] = fmaxf(v[r] + bb, 0.f);
    }
    __syncthreads();

    gemm_j(W2, HID_, HID_ / 32, R1, HID_, sW, tid, j, r0, v);
    {
        float bb = b2[j];
        #pragma unroll
        for (int r = 0; r < 8; r++)
            R0[(r0 + r) * HID_ + j] = fmaxf(v[r] + bb, 0.f);
    }
    __syncthreads();

    gemm_j(W3, HID_, HID_ / 32, R0, HID_, sW, tid, j, r0, v);
    {
        float bb = b3[j];
        #pragma unroll
        for (int r = 0; r < 8; r++) {
            float h = tanhf(v[r] + bb);
            R1[(r0 + r) * HID_ + j] = h;
            if (is_last) last_out[(size_t)(b0 + r0 + r) * HID_ + j] = h;
        }
    }
    __syncthreads();

    gemm_j(Wl, HID_, HID_ / 32, R1, HID_, sW, tid, j, r0, v);
    #pragma unroll
    for (int r = 0; r < 8; r++) {
        int b = b0 + r0 + r;
        out[((size_t)b * WIN_ + step) * HID_ + j] = v[r];
    }
}

// Replicate the reference's upd schedule -> segments (exact double math).
static void host_segments(int* seg_start, int* seg_len, int* nseg) {
    double tu[20];
    for (int j = 0; j < 20; j++) tu[j] = tb_d(50 * j);
    int u_idx[63];
    for (int k = 1; k < 64; k++) {
        double t = tt_d(k);
        int uj = 0;
        for (int j = 0; j < 20; j++) if (tu[j] <= t) uj = j;
        u_idx[k - 1] = uj;
    }
    double qt[64]; int qn = 0, last = -1;
    for (int k = 0; k < 63; k++) {
        int iu = u_idx[k] < 0 ? 0 : u_idx[k];
        if (iu != last) { qt[qn++] = tu[iu]; last = iu; }
    }
    qt[qn++] = tt_d(63);
    bool upd[64]; int qh = 0;
    for (int i = 0; i < 64; i++) {
        upd[i] = false;
        if (qh < qn && tt_d(i) >= qt[qh]) { qh++; upd[i] = true; }
    }
    *nseg = 0; int start = 0;
    for (int i = 0; i < 64; i++) {
        if (upd[i]) { seg_start[*nseg] = start; seg_len[*nseg] = i - start + 1; (*nseg)++; start = i + 1; }
    }
    if (start < 64) { seg_start[*nseg] = start; seg_len[*nseg] = 64 - start; (*nseg)++; }
}

extern "C" void kernel_launch(void* const* d_in, const int* in_sizes, int n_in,
                              void* d_out, int out_size) {
    (void)in_sizes; (void)n_in; (void)out_size;
    const float* z  = (const float*)d_in[0];
    const float* W1 = (const float*)d_in[1];
    const float* b1 = (const float*)d_in[2];
    const float* W2 = (const float*)d_in[3];
    const float* b2 = (const float*)d_in[4];
    const float* W3 = (const float*)d_in[5];
    const float* b3 = (const float*)d_in[6];
    const float* Wl = (const float*)d_in[7];
    float* out = (float*)d_out;

    const size_t smem_bytes =
        (2 * WT_ + BT_ * K1P_ + BT_ * HID_) * sizeof(float);   // ~114 KB
    cudaFuncSetAttribute(rnn_round_kernel,
                         cudaFuncAttributeMaxDynamicSharedMemorySize,
                         (int)smem_bytes);

    sched_kernel<<<1, 256>>>();
    zero_last_kernel<<<(B_ * HID_ + 255) / 256, 256>>>();
    cumsum_part_kernel<<<(B_ * NCH_ * 4) / 256, 256>>>(z);
    cumsum_write_kernel<<<(B_ * NCH_ * 4) / 256, 256>>>(z);
    logsig_kernel<<<dim3(WIN_, B_), 160>>>();

    int seg_start[64], seg_len[64], nseg = 0;
    host_segments(seg_start, seg_len, &nseg);

    int parity = 0;
    for (int s = 0; s < nseg; s++) {
        int grid = seg_len[s] * (B_ / BT_);
        rnn_round_kernel<<<grid, 512, smem_bytes>>>(
            W1, b1, W2, b2, W3, b3, Wl, out, parity, seg_start[s], seg_len[s]);
        parity ^= 1;
    }
}